// round 15
// baseline (speedup 1.0000x reference)
#include <cuda_runtime.h>
#include <cstdint>
#include <math.h>

// ---- problem constants ----
#define BATCH    16
#define KTUP     16384
#define ADDS     32
#define NP       36          // 2^2 + 32 candidates per point
#define DIM      65536       // IN_DIM == OUT_DIM
#define KHALF    8192
#define NPOINTS  (BATCH * KTUP)
#define NCHUNK   16384       // virtual blocks of work
#define GRID_M   1216        // persistent blocks (~152 SMs x occ 8)
#define CPB      14          // chunks per block (1216*14 = 17024 >= 16384)

// scratch: {m0, m1, nh, val} and {npsum, na, nb, -} per (b, k)  (4MB each)
__device__ float4 g_params[NPOINTS];
__device__ float4 g_nbr[NPOINTS];

// =====================================================================
// threefry-2x32, 20 rounds, exactly as jax._src.prng (key = (0, 42)).
// Partitionable mode: counter = (0, flat_index), bits = o0 ^ o1.
// =====================================================================
__device__ __forceinline__ void threefry2x32_42(uint32_t c0, uint32_t c1,
                                                uint32_t& o0, uint32_t& o1) {
    const uint32_t ks0 = 0u;
    const uint32_t ks1 = 42u;
    const uint32_t ks2 = 0x1BD11BDAu ^ 0u ^ 42u;
    uint32_t x0 = c0 + ks0;
    uint32_t x1 = c1 + ks1;
#define TF_R(rot) { x0 += x1; x1 = __funnelshift_l(x1, x1, rot); x1 ^= x0; }
    TF_R(13) TF_R(15) TF_R(26) TF_R(6)   x0 += ks1; x1 += ks2 + 1u;
    TF_R(17) TF_R(29) TF_R(16) TF_R(24)  x0 += ks2; x1 += ks0 + 2u;
    TF_R(13) TF_R(15) TF_R(26) TF_R(6)   x0 += ks0; x1 += ks1 + 3u;
    TF_R(17) TF_R(29) TF_R(16) TF_R(24)  x0 += ks1; x1 += ks2 + 4u;
    TF_R(13) TF_R(15) TF_R(26) TF_R(6)   x0 += ks2; x1 += ks0 + 5u;
#undef TF_R
    o0 = x0; o1 = x1;
}

__device__ __forceinline__ uint32_t jax_random_bits32(uint32_t e) {
    uint32_t o0, o1;
    threefry2x32_42(0u, e, o0, o1);
    return o0 ^ o1;
}

// bits -> JAX index, bit-exact, 1 FFMA (validated rounds 10-14).
__device__ __forceinline__ int bits_to_idx(uint32_t bits) {
    const float C = 0.999999f * 65536.0f;
    float v = __uint_as_float((bits >> 9) | 0x3f800000u);
    return (int)__fmaf_rn(v, C, -C);
}

// ---- sigmoid / softplus: IDENTICAL arithmetic to passing rounds 4-14 ----
__device__ __forceinline__ float xla_sigmoid(float v) {
    float e = expf(-v);
    return __fdiv_rn(1.0f, __fadd_rn(1.0f, e));
}
__device__ __forceinline__ float softplus_f(float v) {
    return fmaxf(v, 0.0f) + log1pf(__expf(-fabsf(v)));
}

// Warp sum via integer redux. Fixed point 2^24: sum <= 36 -> < 2^31.
#define FIXPT 16777216.0f
__device__ __forceinline__ float warp_sum_prop(float v) {
    uint32_t iv = __float2uint_rn(v * FIXPT);
    uint32_t r;
    asm volatile("redux.sync.add.u32 %0, %1, 0xffffffff;" : "=r"(r) : "r"(iv));
    return __uint2float_rn(r) * (1.0f / FIXPT);
}

// Per-point param + neighbor precompute (bit-identical to rounds 13-14).
__device__ __forceinline__ void point_precompute(const float* __restrict__ x,
                                                 float4 r, int idx,
                                                 float4& p, float4& nb4) {
    p.x = __fmul_rn(xla_sigmoid(r.x), 65535.0f);     // m0
    p.y = __fmul_rn(xla_sigmoid(r.y), 65535.0f);     // m1
    float sg = (softplus_f(r.z + 2.0f) + 1e-6f) * 65536.0f;
    p.z = -0.5f / (sg * sg);                         // nh
    p.w = r.w;                                       // val

    const float* xr = x + ((idx >> 14) << 16);       // batch row
    float f0v = floorf(p.x), c0v = ceilf(p.x);
    float f1v = floorf(p.y), c1v = ceilf(p.y);
    float df = f1v - p.y, dc = c1v - p.y;
    float d0a = f0v - p.x;
    float paa = __expf(fmaf(d0a, d0a, df * df) * p.z);
    float pab = __expf(fmaf(d0a, d0a, dc * dc) * p.z);
    float d0b = c0v - p.x;
    float pba = __expf(fmaf(d0b, d0b, df * df) * p.z);
    float pbb = __expf(fmaf(d0b, d0b, dc * dc) * p.z);

    float xf = __ldg(xr + (int)f1v);
    float xc = __ldg(xr + (int)c1v);
    nb4.x = (paa + pab) + (pba + pbb);               // npsum
    nb4.y = fmaf(paa, xf, pab * xc);                 // numerator @ floor(m0)
    nb4.z = fmaf(pba, xf, pbb * xc);                 // numerator @ ceil(m0)
    nb4.w = 0.0f;
}

// =====================================================================
// prolog: blocks [0, 1024)    -> params + neighbors, one point/thread
//         blocks [1024, 2048) -> y[b, o] = bias[o]  (float4)
// Early PDL trigger after each block's stores.
// =====================================================================
__global__ __launch_bounds__(256) void hyper_prolog(const float*  __restrict__ x,
                                                    const float4* __restrict__ res4,
                                                    const float4* __restrict__ bias4,
                                                    float4*       __restrict__ y4) {
    const int b = blockIdx.x;
    const int t = threadIdx.x;
    if (b < 1024) {
        const int i = b * 256 + t;                   // 0 .. NPOINTS-1
        float4 r = __ldg(&res4[i]);
        float4 p, n;
        point_precompute(x, r, i, p, n);
        g_params[i] = p;
        g_nbr[i]    = n;
    } else {
        int i = (b - 1024) * 256 + t;
        y4[i] = __ldg(&bias4[i & (DIM / 4 - 1)]);
    }
    cudaTriggerProgrammaticLaunchCompletion();
}

// =====================================================================
// main (PDL secondary, PERSISTENT): GRID_M blocks, each owning CPB
// consecutive chunks [CPB*j, CPB*j+CPB). One chunk == the round-14
// virtual block: 8 warps, warp -> points (b, kk), (b, kk+8192).
// Chunk i+1's hashes are computed after chunk i's atomics fire,
// pipelining ALU under LSU drain. First chunk's hashes run pre-sync,
// overlapping the prolog on EVERY block (single-wave grid).
// =====================================================================
__global__ __launch_bounds__(256, 8) void hyper_main(const float* __restrict__ x,
                                                     float*       __restrict__ y) {
    const uint32_t wl   = threadIdx.x >> 5;          // warp in block (0..7)
    const uint32_t lane = threadIdx.x & 31u;
    uint32_t c = blockIdx.x * CPB;                   // first chunk

    // ---- chunk-0 hash phase (independent of prolog; overlaps via PDL) ----
    uint32_t w = c * 8u + wl;
    uint32_t i1 = (w >> 13) * KTUP + (w & (KHALF - 1));
    uint32_t e1 = i1 * (ADDS * 2) + lane * 2u;
    uint32_t e2 = e1 + KHALF * (ADDS * 2);
    int si0[2], si1[2];
    si0[0] = bits_to_idx(jax_random_bits32(e1));
    si1[0] = bits_to_idx(jax_random_bits32(e1 + 1u));
    si0[1] = bits_to_idx(jax_random_bits32(e2));
    si1[1] = bits_to_idx(jax_random_bits32(e2 + 1u));

    // ---- wait for prolog (params + neighbors + y-init) ----
    cudaGridDependencySynchronize();

#pragma unroll 1
    for (int it = 0; it < CPB; ++it, ++c) {
        if (c < NCHUNK) {
            const uint32_t b  = w >> 13;
            const uint32_t i2 = i1 + KHALF;

            // ---- precomputed data (warp-uniform broadcast loads) ----
            const float4 p0 = __ldg(&g_params[i1]);
            const float4 p1 = __ldg(&g_params[i2]);
            const float4 n0 = __ldg(&g_nbr[i1]);
            const float4 n1 = __ldg(&g_nbr[i2]);

            // ---- Gaussian props for samples ----
            float d0 = (float)si0[0] - p0.x;
            float d1 = (float)si1[0] - p0.y;
            const float ps0 = __expf(fmaf(d0, d0, d1 * d1) * p0.z);
            d0 = (float)si0[1] - p1.x;
            d1 = (float)si1[1] - p1.y;
            const float ps1 = __expf(fmaf(d0, d0, d1 * d1) * p1.z);

            // ---- normalization (integer redux, validated rounds 9-14) ----
            const float s0 = warp_sum_prop(ps0 + ((lane == 0) ? n0.x : 0.0f));
            const float s1 = warp_sum_prop(ps1 + ((lane == 2) ? n1.x : 0.0f));
            const float sc0 = __fdividef(p0.w, s0 + (float)(NP) * 1e-6f);
            const float sc1 = __fdividef(p1.w, s1 + (float)(NP) * 1e-6f);

            // ---- gather / scatter-add: single batch row ----
            const float* xr = x + (b << 16);
            float*       yr = y + (b << 16);
            atomicAdd(yr + si0[0], sc0 * ps0 * __ldg(xr + si1[0]));
            atomicAdd(yr + si0[1], sc1 * ps1 * __ldg(xr + si1[1]));
            if (lane < 4) {
                const bool hb = lane >= 2;
                const float px  = hb ? p1.x : p0.x;
                const float sc  = hb ? sc1 : sc0;
                const float num = (lane & 1) ? (hb ? n1.z : n0.z)
                                             : (hb ? n1.y : n0.y);
                const int   row = (lane & 1) ? (int)ceilf(px) : (int)floorf(px);
                atomicAdd(yr + row, sc * num);
            }
        }

        // ---- next chunk's hashes (ALU overlaps this chunk's LSU drain) ----
        if (it + 1 < CPB) {
            w  = (c + 1) * 8u + wl;
            i1 = (w >> 13) * KTUP + (w & (KHALF - 1));
            e1 = i1 * (ADDS * 2) + lane * 2u;
            e2 = e1 + KHALF * (ADDS * 2);
            si0[0] = bits_to_idx(jax_random_bits32(e1));
            si1[0] = bits_to_idx(jax_random_bits32(e1 + 1u));
            si0[1] = bits_to_idx(jax_random_bits32(e2));
            si1[1] = bits_to_idx(jax_random_bits32(e2 + 1u));
        }
    }
}

// =====================================================================
extern "C" void kernel_launch(void* const* d_in, const int* in_sizes, int n_in,
                              void* d_out, int out_size) {
    const float*  x     = (const float*)d_in[0];          // (16, 65536)
    const float4* res4  = (const float4*)d_in[1];         // (16, 16384, 4)
    const float4* bias4 = (const float4*)d_in[2];         // (65536,)
    // d_in[3] = temp_indices: fully overwritten by learn_cols -> unused
    float* y = (float*)d_out;                             // (16, 65536)

    hyper_prolog<<<2048, 256>>>(x, res4, bias4, (float4*)y);

    // PDL: persistent main starts during prolog; each block does its
    // first chunk's hash work pre-sync.
    cudaLaunchConfig_t cfg = {};
    cfg.gridDim       = dim3(GRID_M);
    cfg.blockDim      = dim3(256);
    cfg.dynamicSmemBytes = 0;
    cfg.stream        = 0;
    cudaLaunchAttribute attrs[1];
    attrs[0].id = cudaLaunchAttributeProgrammaticStreamSerialization;
    attrs[0].val.programmaticStreamSerializationAllowed = 1;
    cfg.attrs   = attrs;
    cfg.numAttrs = 1;
    cudaLaunchKernelEx(&cfg, hyper_main, x, (float*)y);
}

// round 16
// speedup vs baseline: 1.1249x; 1.1249x over previous
#include <cuda_runtime.h>
#include <cstdint>
#include <math.h>

// ---- problem constants ----
#define BATCH    16
#define KTUP     16384
#define ADDS     32
#define NP       36          // 2^2 + 32 candidates per point
#define DIM      65536       // IN_DIM == OUT_DIM
#define KHALF    8192
#define NPOINTS  (BATCH * KTUP)

// scratch: {m0, m1, nh, val} and {npsum, na, nb, -} per (b, k)  (4MB each)
__device__ float4 g_params[NPOINTS];
__device__ float4 g_nbr[NPOINTS];

// =====================================================================
// threefry-2x32, 20 rounds, exactly as jax._src.prng (key = (0, 42)).
// Partitionable mode: counter = (0, flat_index), bits = o0 ^ o1.
// =====================================================================
__device__ __forceinline__ void threefry2x32_42(uint32_t c0, uint32_t c1,
                                                uint32_t& o0, uint32_t& o1) {
    const uint32_t ks0 = 0u;
    const uint32_t ks1 = 42u;
    const uint32_t ks2 = 0x1BD11BDAu ^ 0u ^ 42u;
    uint32_t x0 = c0 + ks0;
    uint32_t x1 = c1 + ks1;
#define TF_R(rot) { x0 += x1; x1 = __funnelshift_l(x1, x1, rot); x1 ^= x0; }
    TF_R(13) TF_R(15) TF_R(26) TF_R(6)   x0 += ks1; x1 += ks2 + 1u;
    TF_R(17) TF_R(29) TF_R(16) TF_R(24)  x0 += ks2; x1 += ks0 + 2u;
    TF_R(13) TF_R(15) TF_R(26) TF_R(6)   x0 += ks0; x1 += ks1 + 3u;
    TF_R(17) TF_R(29) TF_R(16) TF_R(24)  x0 += ks1; x1 += ks2 + 4u;
    TF_R(13) TF_R(15) TF_R(26) TF_R(6)   x0 += ks2; x1 += ks0 + 5u;
#undef TF_R
    o0 = x0; o1 = x1;
}

__device__ __forceinline__ uint32_t jax_random_bits32(uint32_t e) {
    uint32_t o0, o1;
    threefry2x32_42(0u, e, o0, o1);
    return o0 ^ o1;
}

// bits -> JAX index, bit-exact, 1 FFMA (validated rounds 10-15).
__device__ __forceinline__ int bits_to_idx(uint32_t bits) {
    const float C = 0.999999f * 65536.0f;
    float v = __uint_as_float((bits >> 9) | 0x3f800000u);
    return (int)__fmaf_rn(v, C, -C);
}

// ---- sigmoid / softplus: IDENTICAL arithmetic to passing rounds 4-15 ----
__device__ __forceinline__ float xla_sigmoid(float v) {
    float e = expf(-v);
    return __fdiv_rn(1.0f, __fadd_rn(1.0f, e));
}
__device__ __forceinline__ float softplus_f(float v) {
    return fmaxf(v, 0.0f) + log1pf(__expf(-fabsf(v)));
}

// Warp sum via integer redux. Fixed point 2^24: sum <= 36 -> < 2^31.
#define FIXPT 16777216.0f
__device__ __forceinline__ float warp_sum_prop(float v) {
    uint32_t iv = __float2uint_rn(v * FIXPT);
    uint32_t r;
    asm volatile("redux.sync.add.u32 %0, %1, 0xffffffff;" : "=r"(r) : "r"(iv));
    return __uint2float_rn(r) * (1.0f / FIXPT);
}

// Streaming (evict-first) float4 load: read-once data must not evict the
// L1-resident x-row that the scattered gathers depend on.
__device__ __forceinline__ float4 ldcs4(const float4* p) {
    return __ldcs(p);
}

// Per-point param + neighbor precompute (bit-identical to rounds 13-15).
__device__ __forceinline__ void point_precompute(const float* __restrict__ x,
                                                 float4 r, int idx,
                                                 float4& p, float4& nb4) {
    p.x = __fmul_rn(xla_sigmoid(r.x), 65535.0f);     // m0
    p.y = __fmul_rn(xla_sigmoid(r.y), 65535.0f);     // m1
    float sg = (softplus_f(r.z + 2.0f) + 1e-6f) * 65536.0f;
    p.z = -0.5f / (sg * sg);                         // nh
    p.w = r.w;                                       // val

    const float* xr = x + ((idx >> 14) << 16);       // batch row
    float f0v = floorf(p.x), c0v = ceilf(p.x);
    float f1v = floorf(p.y), c1v = ceilf(p.y);
    float df = f1v - p.y, dc = c1v - p.y;
    float d0a = f0v - p.x;
    float paa = __expf(fmaf(d0a, d0a, df * df) * p.z);
    float pab = __expf(fmaf(d0a, d0a, dc * dc) * p.z);
    float d0b = c0v - p.x;
    float pba = __expf(fmaf(d0b, d0b, df * df) * p.z);
    float pbb = __expf(fmaf(d0b, d0b, dc * dc) * p.z);

    float xf = __ldg(xr + (int)f1v);
    float xc = __ldg(xr + (int)c1v);
    nb4.x = (paa + pab) + (pba + pbb);               // npsum
    nb4.y = fmaf(paa, xf, pab * xc);                 // numerator @ floor(m0)
    nb4.z = fmaf(pba, xf, pbb * xc);                 // numerator @ ceil(m0)
    nb4.w = 0.0f;
}

// =====================================================================
// prolog: blocks [0, 1024)    -> params + neighbors, one point/thread
//         blocks [1024, 2048) -> y[b, o] = bias[o]  (float4)
// Early PDL trigger after each block's stores.
// =====================================================================
__global__ __launch_bounds__(256) void hyper_prolog(const float*  __restrict__ x,
                                                    const float4* __restrict__ res4,
                                                    const float4* __restrict__ bias4,
                                                    float4*       __restrict__ y4) {
    const int b = blockIdx.x;
    const int t = threadIdx.x;
    if (b < 1024) {
        const int i = b * 256 + t;                   // 0 .. NPOINTS-1
        float4 r = __ldg(&res4[i]);
        float4 p, n;
        point_precompute(x, r, i, p, n);
        g_params[i] = p;
        g_nbr[i]    = n;
    } else {
        int i = (b - 1024) * 256 + t;
        __stcs(&y4[i], __ldg(&bias4[i & (DIM / 4 - 1)]));
    }
    cudaTriggerProgrammaticLaunchCompletion();
}

// =====================================================================
// main (PDL secondary): the proven round-13 structure (65.0us). One warp
// per (b, kk) handling (b, kk) and (b, kk+8192). Param/nbr loads are
// STREAMING (__ldcs) so they cannot evict the L1-resident x-row.
// =====================================================================
__global__ __launch_bounds__(256, 8) void hyper_main(const float* __restrict__ x,
                                                     float*       __restrict__ y) {
    const uint32_t w    = blockIdx.x * 8u + (threadIdx.x >> 5);   // 0 .. 131071
    const uint32_t lane = threadIdx.x & 31u;
    const uint32_t b    = w >> 13;           // 0..15
    const uint32_t kk   = w & (KHALF - 1);   // 0..8191

    const uint32_t i1 = b * KTUP + kk;       // point 1: (b, kk)
    const uint32_t i2 = i1 + KHALF;          // point 2: (b, kk+8192)

    // ---- hash phase (independent of prolog; overlaps via PDL) ----
    const uint32_t e1 = i1 * (ADDS * 2) + lane * 2u;
    const uint32_t e2 = e1 + KHALF * (ADDS * 2);
    int si0[2], si1[2];
    si0[0] = bits_to_idx(jax_random_bits32(e1));        // point1 dim0
    si1[0] = bits_to_idx(jax_random_bits32(e1 + 1u));   // point1 dim1
    si0[1] = bits_to_idx(jax_random_bits32(e2));        // point2 dim0
    si1[1] = bits_to_idx(jax_random_bits32(e2 + 1u));   // point2 dim1

    // ---- wait for prolog (params + neighbors + y-init) ----
    cudaGridDependencySynchronize();

    // ---- precomputed data (warp-uniform, STREAMING loads) ----
    const float4 p0 = ldcs4(&g_params[i1]);
    const float4 p1 = ldcs4(&g_params[i2]);
    const float4 n0 = ldcs4(&g_nbr[i1]);
    const float4 n1 = ldcs4(&g_nbr[i2]);

    // ---- Gaussian props for samples ----
    float psamp[2];
    {
        float d0 = (float)si0[0] - p0.x;
        float d1 = (float)si1[0] - p0.y;
        psamp[0] = __expf(fmaf(d0, d0, d1 * d1) * p0.z);
        d0 = (float)si0[1] - p1.x;
        d1 = (float)si1[1] - p1.y;
        psamp[1] = __expf(fmaf(d0, d0, d1 * d1) * p1.z);
    }

    // ---- normalization: den = sum_p props + P*eps (integer redux) ----
    const float s0 = warp_sum_prop(psamp[0] + ((lane == 0) ? n0.x : 0.0f));
    const float s1 = warp_sum_prop(psamp[1] + ((lane == 2) ? n1.x : 0.0f));
    const float sc0 = __fdividef(p0.w, s0 + (float)(NP) * 1e-6f);
    const float sc1 = __fdividef(p1.w, s1 + (float)(NP) * 1e-6f);

    // ---- gather / scatter-add: single batch row (L1-resident) ----
    const float* xr = x + (b << 16);
    float*       yr = y + (b << 16);

    atomicAdd(yr + si0[0], sc0 * psamp[0] * __ldg(xr + si1[0]));
    atomicAdd(yr + si0[1], sc1 * psamp[1] * __ldg(xr + si1[1]));
    if (lane < 4) {
        const bool hb = lane >= 2;                    // point select
        const float px  = hb ? p1.x : p0.x;
        const float sc  = hb ? sc1 : sc0;
        const float num = (lane & 1) ? (hb ? n1.z : n0.z)   // @ceil(m0)
                                     : (hb ? n1.y : n0.y);  // @floor(m0)
        const int   row = (lane & 1) ? (int)ceilf(px) : (int)floorf(px);
        atomicAdd(yr + row, sc * num);
    }
}

// =====================================================================
extern "C" void kernel_launch(void* const* d_in, const int* in_sizes, int n_in,
                              void* d_out, int out_size) {
    const float*  x     = (const float*)d_in[0];          // (16, 65536)
    const float4* res4  = (const float4*)d_in[1];         // (16, 16384, 4)
    const float4* bias4 = (const float4*)d_in[2];         // (65536,)
    // d_in[3] = temp_indices: fully overwritten by learn_cols -> unused
    float* y = (float*)d_out;                             // (16, 65536)

    hyper_prolog<<<2048, 256>>>(x, res4, bias4, (float4*)y);

    // PDL: main may start early; it self-synchronizes via
    // cudaGridDependencySynchronize() before touching prolog outputs.
    cudaLaunchConfig_t cfg = {};
    cfg.gridDim       = dim3((BATCH * KHALF) / 8);        // 16384 blocks
    cfg.blockDim      = dim3(256);
    cfg.dynamicSmemBytes = 0;
    cfg.stream        = 0;
    cudaLaunchAttribute attrs[1];
    attrs[0].id = cudaLaunchAttributeProgrammaticStreamSerialization;
    attrs[0].val.programmaticStreamSerializationAllowed = 1;
    cfg.attrs   = attrs;
    cfg.numAttrs = 1;
    cudaLaunchKernelEx(&cfg, hyper_main, x, (float*)y);
}